// round 2
// baseline (speedup 1.0000x reference)
#include <cuda_runtime.h>
#include <cuda_bf16.h>
#include <math.h>

#define N_PIX 2304
#define C_DIM 128
#define NHEAD 4
#define HC 32
#define K_CL 16
#define INV_SCALE 0.17677669529663687f   // 1/sqrt(32)

// ---------------- scratch (device globals; no allocation allowed) ----------------
__device__ __align__(256) float g_q[N_PIX * C_DIM];
__device__ __align__(256) float g_k[N_PIX * C_DIM];
__device__ __align__(256) float g_v[N_PIX * C_DIM];
__device__ __align__(256) float g_kp[N_PIX * C_DIM];     // k sorted by label
__device__ __align__(256) float g_vp[N_PIX * C_DIM];     // v sorted by label
__device__ __align__(256) float g_centers[K_CL * C_DIM];
__device__ __align__(256) float g_pcp[(size_t)N_PIX * N_PIX];  // pc permuted both dims (21 MB)
__device__ __align__(256) float g_attn[N_PIX * C_DIM];
__device__ __align__(256) float g_h1[N_PIX * 2 * C_DIM];
__device__ __align__(256) float g_rs1[N_PIX * C_DIM];
__device__ __align__(256) float g_h2[N_PIX * 2 * C_DIM];
__device__ int g_order[N_PIX];   // sorted index -> original pixel
__device__ int g_labs[N_PIX];    // labels in sorted order

// ---------------- generic tiled GEMM body: out[M,Kout] = A @ W + bias ----------------
// TRANS_A: A stored [Kin][M] (channel-major image). Else A is [M][Kin].
// Tile: 64 rows x 64 cols, 256 threads, 4x4 micro-tile, Ktile=32.
template <bool TRANS_A, bool LEAKY, bool RES, bool TRANS_OUT>
__device__ __forceinline__ void gemm_body(
    const float* __restrict__ A, const float* __restrict__ W,
    const float* __restrict__ bias, const float* __restrict__ res,
    float* __restrict__ out, int M, int Kin, int Kout)
{
    __shared__ __align__(16) float As[32][68];
    __shared__ __align__(16) float Bs[32][68];
    const int m0 = blockIdx.x * 64;
    const int c0 = blockIdx.y * 64;
    const int tid = threadIdx.x;
    const int tr = tid >> 4;   // 0..15
    const int tc = tid & 15;   // 0..15

    float acc[4][4];
#pragma unroll
    for (int r = 0; r < 4; r++)
#pragma unroll
        for (int c = 0; c < 4; c++) acc[r][c] = 0.f;

    for (int k0 = 0; k0 < Kin; k0 += 32) {
#pragma unroll
        for (int p = 0; p < 8; p++) {
            int idx = tid + p * 256;             // 0..2047
            if (TRANS_A) {
                int kk = idx >> 6, mm = idx & 63;
                As[kk][mm] = A[(size_t)(k0 + kk) * M + m0 + mm];
            } else {
                int row = idx >> 5, kk = idx & 31;
                As[kk][row] = A[(size_t)(m0 + row) * Kin + k0 + kk];
            }
            int kk2 = idx >> 6, cc = idx & 63;
            Bs[kk2][cc] = W[(size_t)(k0 + kk2) * Kout + c0 + cc];
        }
        __syncthreads();
#pragma unroll
        for (int kk = 0; kk < 32; kk++) {
            float4 a4 = *(const float4*)&As[kk][tr * 4];
            float4 b4 = *(const float4*)&Bs[kk][tc * 4];
            float av[4] = {a4.x, a4.y, a4.z, a4.w};
            float bv[4] = {b4.x, b4.y, b4.z, b4.w};
#pragma unroll
            for (int r = 0; r < 4; r++)
#pragma unroll
                for (int c = 0; c < 4; c++) acc[r][c] += av[r] * bv[c];
        }
        __syncthreads();
    }
#pragma unroll
    for (int r = 0; r < 4; r++) {
#pragma unroll
        for (int c = 0; c < 4; c++) {
            int m = m0 + tr * 4 + r;
            int cc = c0 + tc * 4 + c;
            float v = acc[r][c] + bias[cc];
            if (LEAKY) v = v > 0.f ? v : 0.01f * v;
            if (RES) v += res[(size_t)m * C_DIM + cc];
            if (TRANS_OUT) out[(size_t)cc * M + m] = v;
            else out[(size_t)m * Kout + cc] = v;
        }
    }
}

// ---------------- kernels ----------------

// 3 projections batched over blockIdx.z. grid (36, 2, 3)
__global__ void __launch_bounds__(256) k_proj(
    const float* x0, const float* x1, const float* x2,
    const float* w0, const float* w1, const float* w2,
    const float* b0, const float* b1, const float* b2)
{
    const float* A; const float* W; const float* B; float* O;
    if (blockIdx.z == 0)      { A = x0; W = w0; B = b0; O = g_q; }
    else if (blockIdx.z == 1) { A = x1; W = w1; B = b1; O = g_k; }
    else                      { A = x2; W = w2; B = b2; O = g_v; }
    gemm_body<true, false, false, false>(A, W, B, nullptr, O, N_PIX, C_DIM, C_DIM);
}

// cluster centers from projected k. grid (16), 512 threads (4 pixel-stripes x 128 ch)
__global__ void __launch_bounds__(512) k_centers(const int* __restrict__ labels)
{
    __shared__ float ssum[4][C_DIM];
    __shared__ int scnt[4];
    const int cl = blockIdx.x;
    const int s = threadIdx.x >> 7;     // 0..3
    const int c = threadIdx.x & 127;
    float sum = 0.f; int cnt = 0;
    const int n0 = s * (N_PIX / 4), n1 = n0 + (N_PIX / 4);
    for (int n = n0; n < n1; n++) {
        if (labels[n] == cl) { sum += g_k[(size_t)n * C_DIM + c]; cnt++; }
    }
    ssum[s][c] = sum;
    if (c == 0) scnt[s] = cnt;
    __syncthreads();
    if (s == 0) {
        float t = ssum[0][c] + ssum[1][c] + ssum[2][c] + ssum[3][c];
        int ct = scnt[0] + scnt[1] + scnt[2] + scnt[3];
        g_centers[cl * C_DIM + c] = t / ((float)ct + 1e-6f);
    }
}

// counting sort of pixels by label. single block.
__global__ void __launch_bounds__(256) k_sort(const int* __restrict__ labels)
{
    __shared__ int cnt[K_CL];
    __shared__ int off[K_CL];
    const int tid = threadIdx.x;
    if (tid < K_CL) cnt[tid] = 0;
    __syncthreads();
    for (int n = tid; n < N_PIX; n += 256) atomicAdd(&cnt[labels[n]], 1);
    __syncthreads();
    if (tid == 0) {
        int run = 0;
        for (int kk = 0; kk < K_CL; kk++) { off[kk] = run; run += cnt[kk]; }
    }
    __syncthreads();
    for (int n = tid; n < N_PIX; n += 256) {
        int l = labels[n];
        int p = atomicAdd(&off[l], 1);
        g_order[p] = n;
        g_labs[p] = l;
    }
}

// permute k, v, and pc (both dims) into sorted order. grid (N_PIX), 256 threads
__global__ void __launch_bounds__(256) k_permute(const float* __restrict__ pc)
{
    __shared__ int sord[N_PIX];
    const int tid = threadIdx.x;
    const int ii = blockIdx.x;
    for (int t = tid; t < N_PIX; t += 256) sord[t] = g_order[t];
    __syncthreads();
    const int src = sord[ii];
    if (tid < 128) {
        g_kp[(size_t)ii * C_DIM + tid] = g_k[(size_t)src * C_DIM + tid];
        g_vp[(size_t)ii * C_DIM + tid] = g_v[(size_t)src * C_DIM + tid];
    }
    const float* prow = pc + (size_t)src * N_PIX;
    float* orow = g_pcp + (size_t)ii * N_PIX;
    for (int jj = tid; jj < N_PIX; jj += 256) orow[jj] = prow[sord[jj]];
}

// attention: grid (N_PIX/8, NHEAD), 256 threads, one warp per (sorted query, head).
// Max-free streaming softmax; per-lane partial 32-dim accumulators; dot only for
// same-cluster chunks (keys are label-sorted so chunks are nearly label-uniform).
__global__ void __launch_bounds__(256, 2) k_attn()
{
    const int h = blockIdx.y;
    const int warp = threadIdx.x >> 5;
    const int lane = threadIdx.x & 31;
    const int ii = blockIdx.x * 8 + warp;   // sorted query index
    const int i = g_order[ii];              // original pixel
    const int mylab = g_labs[ii];
    const int hd = h * HC;

    float qv[HC];
    {
        const float4* qp = (const float4*)(g_q + (size_t)i * C_DIM + hd);
#pragma unroll
        for (int t = 0; t < 8; t++) {
            float4 f = __ldg(qp + t);
            qv[4 * t + 0] = f.x * INV_SCALE;
            qv[4 * t + 1] = f.y * INV_SCALE;
            qv[4 * t + 2] = f.z * INV_SCALE;
            qv[4 * t + 3] = f.w * INV_SCALE;
        }
    }
    // lane k (k<16) holds cscore[k] = (q_i/sqrt(d)) . center_k  (head slice)
    float csr = 0.f;
    {
        const int cl = lane & 15;
        const float4* cp = (const float4*)(g_centers + cl * C_DIM + hd);
#pragma unroll
        for (int t = 0; t < 8; t++) {
            float4 f = __ldg(cp + t);
            csr += qv[4 * t + 0] * f.x + qv[4 * t + 1] * f.y
                 + qv[4 * t + 2] * f.z + qv[4 * t + 3] * f.w;
        }
    }

    float S = 0.f;
    float acc[HC];
#pragma unroll
    for (int d = 0; d < HC; d++) acc[d] = 0.f;

    const float* pcrow = g_pcp + (size_t)ii * N_PIX;

    for (int j0 = 0; j0 < N_PIX; j0 += 32) {
        const int j = j0 + lane;
        const int lj = g_labs[j];
        const float pcv = __ldg(pcrow + j);
        const bool same = (lj == mylab);
        float s;
        if (__ballot_sync(0xffffffffu, same)) {
            float d = 0.f;
            const float4* kr = (const float4*)(g_kp + (size_t)j * C_DIM + hd);
#pragma unroll
            for (int t = 0; t < 8; t++) {
                float4 f = __ldg(kr + t);
                d += qv[4 * t + 0] * f.x + qv[4 * t + 1] * f.y
                   + qv[4 * t + 2] * f.z + qv[4 * t + 3] * f.w;
            }
            float si = __shfl_sync(0xffffffffu, csr, lj) * pcv;
            s = same ? d : si;
        } else {
            s = __shfl_sync(0xffffffffu, csr, lj) * pcv;
        }
        const float p = __expf(s);   // max-free: |s| is O(1) for this workload
        S += p;
        const float4* vr = (const float4*)(g_vp + (size_t)j * C_DIM + hd);
#pragma unroll
        for (int t = 0; t < 8; t++) {
            float4 f = __ldg(vr + t);
            acc[4 * t + 0] += p * f.x;
            acc[4 * t + 1] += p * f.y;
            acc[4 * t + 2] += p * f.z;
            acc[4 * t + 3] += p * f.w;
        }
    }

    // butterfly-reduce S and the 32-dim accumulator across lanes
#pragma unroll
    for (int off = 16; off; off >>= 1) {
        S += __shfl_xor_sync(0xffffffffu, S, off);
#pragma unroll
        for (int d = 0; d < HC; d++) acc[d] += __shfl_xor_sync(0xffffffffu, acc[d], off);
    }
    if (lane == 0) {
        const float invS = 1.f / S;
        float4* op = (float4*)(g_attn + (size_t)i * C_DIM + hd);
#pragma unroll
        for (int t = 0; t < 8; t++) {
            op[t] = make_float4(acc[4 * t + 0] * invS, acc[4 * t + 1] * invS,
                                acc[4 * t + 2] * invS, acc[4 * t + 3] * invS);
        }
    }
}

// MLP stages
__global__ void __launch_bounds__(256) k_mlp1a(const float* W, const float* b) {
    gemm_body<false, true, false, false>(g_attn, W, b, nullptr, g_h1, N_PIX, 128, 256);
}
__global__ void __launch_bounds__(256) k_mlp1b(const float* W, const float* b) {
    gemm_body<false, false, true, false>(g_h1, W, b, g_v, g_rs1, N_PIX, 256, 128);
}
__global__ void __launch_bounds__(256) k_mlp2a(const float* W, const float* b) {
    gemm_body<false, true, false, false>(g_rs1, W, b, nullptr, g_h2, N_PIX, 128, 256);
}
__global__ void __launch_bounds__(256) k_mlp2b(const float* W, const float* b, float* o) {
    gemm_body<false, false, true, true>(g_h2, W, b, g_rs1, o, N_PIX, 256, 128);
}

// ---------------- launch ----------------
extern "C" void kernel_launch(void* const* d_in, const int* in_sizes, int n_in,
                              void* d_out, int out_size)
{
    // setup_inputs() dict order
    const float* q_img  = (const float*)d_in[0];
    const float* k_img  = (const float*)d_in[1];
    const float* v_img  = (const float*)d_in[2];
    const float* pc     = (const float*)d_in[3];
    const int*   labels = (const int*)  d_in[4];
    const float* wq  = (const float*)d_in[5];
    const float* bq  = (const float*)d_in[6];
    const float* wk  = (const float*)d_in[7];
    const float* bk  = (const float*)d_in[8];
    const float* wv  = (const float*)d_in[9];
    const float* bv  = (const float*)d_in[10];
    const float* w1a = (const float*)d_in[11];
    const float* b1a = (const float*)d_in[12];
    const float* w1b = (const float*)d_in[13];
    const float* b1b = (const float*)d_in[14];
    const float* w2a = (const float*)d_in[15];
    const float* b2a = (const float*)d_in[16];
    const float* w2b = (const float*)d_in[17];
    const float* b2b = (const float*)d_in[18];
    float* out = (float*)d_out;

    dim3 gproj(N_PIX / 64, 2, 3);
    k_proj<<<gproj, 256>>>(q_img, k_img, v_img, wq, wk, wv, bq, bk, bv);
    k_centers<<<K_CL, 512>>>(labels);
    k_sort<<<1, 256>>>(labels);
    k_permute<<<N_PIX, 256>>>(pc);
    dim3 gattn(N_PIX / 8, NHEAD);
    k_attn<<<gattn, 256>>>();
    k_mlp1a<<<dim3(N_PIX / 64, 4), 256>>>(w1a, b1a);
    k_mlp1b<<<dim3(N_PIX / 64, 2), 256>>>(w1b, b1b);
    k_mlp2a<<<dim3(N_PIX / 64, 4), 256>>>(w2a, b2a);
    k_mlp2b<<<dim3(N_PIX / 64, 2), 256>>>(w2b, b2b, out);
}

// round 3
// speedup vs baseline: 3.6635x; 3.6635x over previous
#include <cuda_runtime.h>
#include <cuda_bf16.h>
#include <math.h>

#define N_PIX 2304
#define C_DIM 128
#define NHEAD 4
#define HC 32
#define K_CL 16
#define INV_SCALE 0.17677669529663687f   // 1/sqrt(32)
#define QB 16                            // queries per attention block
#define NCH (N_PIX / 32)                 // 72 key chunks

// ---------------- scratch (device globals; no allocation allowed) ----------------
__device__ __align__(256) float g_q[N_PIX * C_DIM];
__device__ __align__(256) float g_k[N_PIX * C_DIM];
__device__ __align__(256) float g_v[N_PIX * C_DIM];
__device__ __align__(256) float g_kp[N_PIX * C_DIM];     // k sorted by label
__device__ __align__(256) float g_vp[N_PIX * C_DIM];     // v sorted by label
__device__ __align__(256) float g_centers[K_CL * C_DIM];
__device__ __align__(256) float g_pcp[(size_t)N_PIX * N_PIX];  // pc permuted both dims
__device__ __align__(256) float g_attn[N_PIX * C_DIM];
__device__ __align__(256) float g_h1[N_PIX * 2 * C_DIM];
__device__ __align__(256) float g_rs1[N_PIX * C_DIM];
__device__ __align__(256) float g_h2[N_PIX * 2 * C_DIM];
__device__ int g_order[N_PIX];   // sorted index -> original pixel (stable)
__device__ int g_labs[N_PIX];    // labels in sorted order

// ---------------- generic tiled GEMM body: out[M,Kout] = A @ W + bias ----------------
template <bool TRANS_A, bool LEAKY, bool RES, bool TRANS_OUT>
__device__ __forceinline__ void gemm_body(
    const float* __restrict__ A, const float* __restrict__ W,
    const float* __restrict__ bias, const float* __restrict__ res,
    float* __restrict__ out, int M, int Kin, int Kout)
{
    __shared__ __align__(16) float As[32][68];
    __shared__ __align__(16) float Bs[32][68];
    const int m0 = blockIdx.x * 64;
    const int c0 = blockIdx.y * 64;
    const int tid = threadIdx.x;
    const int tr = tid >> 4;   // 0..15
    const int tc = tid & 15;   // 0..15

    float acc[4][4];
#pragma unroll
    for (int r = 0; r < 4; r++)
#pragma unroll
        for (int c = 0; c < 4; c++) acc[r][c] = 0.f;

    for (int k0 = 0; k0 < Kin; k0 += 32) {
#pragma unroll
        for (int p = 0; p < 8; p++) {
            int idx = tid + p * 256;             // 0..2047
            if (TRANS_A) {
                int kk = idx >> 6, mm = idx & 63;
                As[kk][mm] = A[(size_t)(k0 + kk) * M + m0 + mm];
            } else {
                int row = idx >> 5, kk = idx & 31;
                As[kk][row] = A[(size_t)(m0 + row) * Kin + k0 + kk];
            }
            int kk2 = idx >> 6, cc = idx & 63;
            Bs[kk2][cc] = W[(size_t)(k0 + kk2) * Kout + c0 + cc];
        }
        __syncthreads();
#pragma unroll
        for (int kk = 0; kk < 32; kk++) {
            float4 a4 = *(const float4*)&As[kk][tr * 4];
            float4 b4 = *(const float4*)&Bs[kk][tc * 4];
            float av[4] = {a4.x, a4.y, a4.z, a4.w};
            float bv[4] = {b4.x, b4.y, b4.z, b4.w};
#pragma unroll
            for (int r = 0; r < 4; r++)
#pragma unroll
                for (int c = 0; c < 4; c++) acc[r][c] += av[r] * bv[c];
        }
        __syncthreads();
    }
#pragma unroll
    for (int r = 0; r < 4; r++) {
#pragma unroll
        for (int c = 0; c < 4; c++) {
            int m = m0 + tr * 4 + r;
            int cc = c0 + tc * 4 + c;
            float v = acc[r][c] + bias[cc];
            if (LEAKY) v = v > 0.f ? v : 0.01f * v;
            if (RES) v += res[(size_t)m * C_DIM + cc];
            if (TRANS_OUT) out[(size_t)cc * M + m] = v;
            else out[(size_t)m * Kout + cc] = v;
        }
    }
}

// ---------------- kernels ----------------

// 3 projections batched over blockIdx.z. grid (36, 2, 3)
__global__ void __launch_bounds__(256) k_proj(
    const float* x0, const float* x1, const float* x2,
    const float* w0, const float* w1, const float* w2,
    const float* b0, const float* b1, const float* b2)
{
    const float* A; const float* W; const float* B; float* O;
    if (blockIdx.z == 0)      { A = x0; W = w0; B = b0; O = g_q; }
    else if (blockIdx.z == 1) { A = x1; W = w1; B = b1; O = g_k; }
    else                      { A = x2; W = w2; B = b2; O = g_v; }
    gemm_body<true, false, false, false>(A, W, B, nullptr, O, N_PIX, C_DIM, C_DIM);
}

// cluster centers from projected k. grid (16), 512 threads
__global__ void __launch_bounds__(512) k_centers(const int* __restrict__ labels)
{
    __shared__ float ssum[4][C_DIM];
    __shared__ int scnt[4];
    const int cl = blockIdx.x;
    const int s = threadIdx.x >> 7;     // 0..3
    const int c = threadIdx.x & 127;
    float sum = 0.f; int cnt = 0;
    const int n0 = s * (N_PIX / 4), n1 = n0 + (N_PIX / 4);
    for (int n = n0; n < n1; n++) {
        if (labels[n] == cl) { sum += g_k[(size_t)n * C_DIM + c]; cnt++; }
    }
    ssum[s][c] = sum;
    if (c == 0) scnt[s] = cnt;
    __syncthreads();
    if (s == 0) {
        float t = ssum[0][c] + ssum[1][c] + ssum[2][c] + ssum[3][c];
        int ct = scnt[0] + scnt[1] + scnt[2] + scnt[3];
        g_centers[cl * C_DIM + c] = t / ((float)ct + 1e-6f);
    }
}

// STABLE counting sort of pixels by label. single block, 256 threads, no atomics.
__global__ void __launch_bounds__(256) k_sort(const int* __restrict__ labels)
{
    __shared__ int cnt[K_CL][257];
    __shared__ int gsum[K_CL][17];
    __shared__ int base[K_CL];
    const int tid = threadIdx.x;
    const int per = N_PIX / 256;   // 9
#pragma unroll
    for (int l = 0; l < K_CL; l++) cnt[l][tid] = 0;
    __syncthreads();
    int myl[9];
#pragma unroll
    for (int u = 0; u < per; u++) {
        int l = labels[tid * per + u];
        myl[u] = l;
        cnt[l][tid]++;
    }
    __syncthreads();
    // two-level exclusive scan across t for each label
    {
        int l = tid >> 4, g = tid & 15;
        int s = 0;
#pragma unroll
        for (int k2 = 0; k2 < 16; k2++) s += cnt[l][g * 16 + k2];
        gsum[l][g] = s;
    }
    __syncthreads();
    if (tid < K_CL) {
        int run = 0;
        for (int g = 0; g < 16; g++) { int t = gsum[tid][g]; gsum[tid][g] = run; run += t; }
        gsum[tid][16] = run;   // label total
    }
    __syncthreads();
    if (tid == 0) {
        int run = 0;
        for (int l = 0; l < K_CL; l++) { base[l] = run; run += gsum[l][16]; }
    }
    __syncthreads();
    {
        int l = tid >> 4, g = tid & 15;
        int run = gsum[l][g];
#pragma unroll
        for (int k2 = 0; k2 < 16; k2++) { int t = cnt[l][g * 16 + k2]; cnt[l][g * 16 + k2] = run; run += t; }
    }
    __syncthreads();
#pragma unroll
    for (int u = 0; u < per; u++) {
        int l = myl[u];
        int p = base[l] + cnt[l][tid]++;
        g_order[p] = tid * per + u;
        g_labs[p] = l;
    }
}

// permute k, v, and pc (both dims) into sorted order. grid (N_PIX), 256 threads
__global__ void __launch_bounds__(256) k_permute(const float* __restrict__ pc)
{
    __shared__ int sord[N_PIX];
    const int tid = threadIdx.x;
    const int ii = blockIdx.x;
    for (int t = tid; t < N_PIX; t += 256) sord[t] = g_order[t];
    __syncthreads();
    const int src = sord[ii];
    if (tid < 128) {
        g_kp[(size_t)ii * C_DIM + tid] = g_k[(size_t)src * C_DIM + tid];
        g_vp[(size_t)ii * C_DIM + tid] = g_v[(size_t)src * C_DIM + tid];
    }
    const float* prow = pc + (size_t)src * N_PIX;
    float* orow = g_pcp + (size_t)ii * N_PIX;
    for (int jj = tid; jj < N_PIX; jj += 256) orow[jj] = prow[sord[jj]];
}

// attention: grid (N_PIX/QB, NHEAD), 512 threads = 16 warps, one warp per query.
// Smem-staged, double-buffered k/v chunks; phase1 lane=key (scores), phase2
// lane=dim (AV from conflict-free smem, scalar accumulators).
__global__ void __launch_bounds__(512, 3) k_attn()
{
    const int h = blockIdx.y, hd = h * HC;
    const int tid = threadIdx.x;
    const int warp = tid >> 5, lane = tid & 31;
    const int ii = blockIdx.x * QB + warp;       // sorted query index
    const int i = g_order[ii];                   // original pixel
    const int mylab = g_labs[ii];
    const int minLab = __ldg(&g_labs[blockIdx.x * QB]);
    const int maxLab = __ldg(&g_labs[blockIdx.x * QB + QB - 1]);

    __shared__ float ks[2][32][33];
    __shared__ float vs[2][32][33];
    __shared__ __align__(16) float qsm[QB][36];
    __shared__ __align__(16) float ps[QB][36];
    __shared__ int labsm[2][32];

    // stage scaled q into smem (per-warp row)
    qsm[warp][lane] = g_q[(size_t)i * C_DIM + hd + lane] * INV_SCALE;
    __syncwarp();

    // center scores: lane k (k<16) holds q . center_k
    float csr = 0.f;
    {
        const int cl = lane & 15;
        const float4* cp = (const float4*)(g_centers + cl * C_DIM + hd);
#pragma unroll
        for (int t = 0; t < 8; t++) {
            float4 f = __ldg(cp + t);
            float4 q4 = *(const float4*)&qsm[warp][4 * t];
            csr += q4.x * f.x + q4.y * f.y + q4.z * f.z + q4.w * f.w;
        }
    }

    const float* pcrow = g_pcp + (size_t)ii * N_PIX;

    // staging map: thread owns elements (r, c2) and (r, c2+1) of the 32x32 tile
    const int r = tid >> 4;
    const int c2 = (tid & 15) * 2;

    // stage chunk 0
    {
        const float2 v2 = *(const float2*)&g_vp[(size_t)r * C_DIM + hd + c2];
        vs[0][r][c2] = v2.x; vs[0][r][c2 + 1] = v2.y;
        int l0 = __ldg(&g_labs[0]), l1 = __ldg(&g_labs[31]);
        if (l1 >= minLab && l0 <= maxLab) {
            const float2 k2 = *(const float2*)&g_kp[(size_t)r * C_DIM + hd + c2];
            ks[0][r][c2] = k2.x; ks[0][r][c2 + 1] = k2.y;
        }
        if (tid < 32) labsm[0][tid] = g_labs[tid];
    }
    float pccur = __ldg(&pcrow[lane]);
    __syncthreads();

    float acc0 = 0.f, acc1 = 0.f, acc2 = 0.f, acc3 = 0.f, Sl = 0.f;
    int buf = 0;
    for (int ch = 0; ch < NCH; ch++) {
        // prefetch next chunk into registers (overlaps LDG latency with compute)
        float2 vpre = make_float2(0.f, 0.f), kpre = make_float2(0.f, 0.f);
        int lpre = 0; bool kneed = false; float pcpre = 0.f;
        if (ch + 1 < NCH) {
            const int j0n = (ch + 1) * 32;
            vpre = *(const float2*)&g_vp[(size_t)(j0n + r) * C_DIM + hd + c2];
            int l0 = __ldg(&g_labs[j0n]), l1 = __ldg(&g_labs[j0n + 31]);
            kneed = (l1 >= minLab && l0 <= maxLab);
            if (kneed)
                kpre = *(const float2*)&g_kp[(size_t)(j0n + r) * C_DIM + hd + c2];
            if (tid < 32) lpre = __ldg(&g_labs[j0n + tid]);
            pcpre = __ldg(&pcrow[j0n + lane]);
        }

        // phase 1: lane = key
        const int lj = labsm[buf][lane];
        float s = __shfl_sync(0xffffffffu, csr, lj) * pccur;
        const bool same = (lj == mylab);
        if (__ballot_sync(0xffffffffu, same)) {
            float d0 = 0.f, d1 = 0.f;
#pragma unroll
            for (int t = 0; t < 8; t++) {
                float4 q4 = *(const float4*)&qsm[warp][4 * t];
                d0 += q4.x * ks[buf][lane][4 * t + 0] + q4.y * ks[buf][lane][4 * t + 1];
                d1 += q4.z * ks[buf][lane][4 * t + 2] + q4.w * ks[buf][lane][4 * t + 3];
            }
            if (same) s = d0 + d1;
        }
        const float p = __expf(s);   // max-free: |s| is O(1) for this workload
        Sl += p;
        ps[warp][lane] = p;
        __syncwarp();

        // phase 2: lane = dim; conflict-free smem, broadcast p via float4
#pragma unroll
        for (int jq = 0; jq < 32; jq += 4) {
            float4 p4 = *(const float4*)&ps[warp][jq];
            acc0 += p4.x * vs[buf][jq + 0][lane];
            acc1 += p4.y * vs[buf][jq + 1][lane];
            acc2 += p4.z * vs[buf][jq + 2][lane];
            acc3 += p4.w * vs[buf][jq + 3][lane];
        }

        // commit prefetched chunk into the other buffer
        if (ch + 1 < NCH) {
            const int nb = buf ^ 1;
            vs[nb][r][c2] = vpre.x; vs[nb][r][c2 + 1] = vpre.y;
            if (kneed) { ks[nb][r][c2] = kpre.x; ks[nb][r][c2 + 1] = kpre.y; }
            if (tid < 32) labsm[nb][tid] = lpre;
            pccur = pcpre;
        }
        buf ^= 1;
        __syncthreads();
    }

    float S = Sl;
#pragma unroll
    for (int off = 16; off; off >>= 1) S += __shfl_xor_sync(0xffffffffu, S, off);
    g_attn[(size_t)i * C_DIM + hd + lane] = (acc0 + acc1 + acc2 + acc3) / S;
}

// MLP stages
__global__ void __launch_bounds__(256) k_mlp1a(const float* W, const float* b) {
    gemm_body<false, true, false, false>(g_attn, W, b, nullptr, g_h1, N_PIX, 128, 256);
}
__global__ void __launch_bounds__(256) k_mlp1b(const float* W, const float* b) {
    gemm_body<false, false, true, false>(g_h1, W, b, g_v, g_rs1, N_PIX, 256, 128);
}
__global__ void __launch_bounds__(256) k_mlp2a(const float* W, const float* b) {
    gemm_body<false, true, false, false>(g_rs1, W, b, nullptr, g_h2, N_PIX, 128, 256);
}
__global__ void __launch_bounds__(256) k_mlp2b(const float* W, const float* b, float* o) {
    gemm_body<false, false, true, true>(g_h2, W, b, g_rs1, o, N_PIX, 256, 128);
}

// ---------------- launch ----------------
extern "C" void kernel_launch(void* const* d_in, const int* in_sizes, int n_in,
                              void* d_out, int out_size)
{
    const float* q_img  = (const float*)d_in[0];
    const float* k_img  = (const float*)d_in[1];
    const float* v_img  = (const float*)d_in[2];
    const float* pc     = (const float*)d_in[3];
    const int*   labels = (const int*)  d_in[4];
    const float* wq  = (const float*)d_in[5];
    const float* bq  = (const float*)d_in[6];
    const float* wk  = (const float*)d_in[7];
    const float* bk  = (const float*)d_in[8];
    const float* wv  = (const float*)d_in[9];
    const float* bv  = (const float*)d_in[10];
    const float* w1a = (const float*)d_in[11];
    const float* b1a = (const float*)d_in[12];
    const float* w1b = (const float*)d_in[13];
    const float* b1b = (const float*)d_in[14];
    const float* w2a = (const float*)d_in[15];
    const float* b2a = (const float*)d_in[16];
    const float* w2b = (const float*)d_in[17];
    const float* b2b = (const float*)d_in[18];
    float* out = (float*)d_out;

    dim3 gproj(N_PIX / 64, 2, 3);
    k_proj<<<gproj, 256>>>(q_img, k_img, v_img, wq, wk, wv, bq, bk, bv);
    k_centers<<<K_CL, 512>>>(labels);
    k_sort<<<1, 256>>>(labels);
    k_permute<<<N_PIX, 256>>>(pc);
    dim3 gattn(N_PIX / QB, NHEAD);
    k_attn<<<gattn, 512>>>();
    k_mlp1a<<<dim3(N_PIX / 64, 4), 256>>>(w1a, b1a);
    k_mlp1b<<<dim3(N_PIX / 64, 2), 256>>>(w1b, b1b);
    k_mlp2a<<<dim3(N_PIX / 64, 4), 256>>>(w2a, b2a);
    k_mlp2b<<<dim3(N_PIX / 64, 2), 256>>>(w2b, b2b, out);
}

// round 5
// speedup vs baseline: 5.5555x; 1.5164x over previous
#include <cuda_runtime.h>
#include <cuda_bf16.h>
#include <math.h>

#define N_PIX 2304
#define C_DIM 128
#define NHEAD 4
#define HC 32
#define K_CL 16
#define INV_SCALE 0.17677669529663687f   // 1/sqrt(32)
#define QB 32                            // queries per attention block
#define QW 4                             // queries per warp
#define NCH (N_PIX / 32)                 // 72 key chunks

// ---------------- scratch (device globals; no allocation allowed) ----------------
__device__ __align__(256) float g_q[N_PIX * C_DIM];
__device__ __align__(256) float g_k[N_PIX * C_DIM];
__device__ __align__(256) float g_v[N_PIX * C_DIM];
__device__ __align__(256) float g_kp[N_PIX * C_DIM];     // k sorted by label
__device__ __align__(256) float g_vp[N_PIX * C_DIM];     // v sorted by label
__device__ __align__(256) float g_centers[K_CL * C_DIM];
__device__ __align__(256) float g_pcp[(size_t)N_PIX * N_PIX];  // pc permuted both dims
__device__ __align__(256) float g_attn[N_PIX * C_DIM];
__device__ __align__(256) float g_h1[N_PIX * 2 * C_DIM];
__device__ __align__(256) float g_rs1[N_PIX * C_DIM];
__device__ __align__(256) float g_h2[N_PIX * 2 * C_DIM];
__device__ int g_order[N_PIX];   // sorted index -> original pixel (stable)
__device__ int g_labs[N_PIX];    // labels in sorted order

// ---------------- generic tiled GEMM body: out[M,Kout] = A @ W + bias ----------------
template <bool TRANS_A, bool LEAKY, bool RES, bool TRANS_OUT>
__device__ __forceinline__ void gemm_body(
    const float* __restrict__ A, const float* __restrict__ W,
    const float* __restrict__ bias, const float* __restrict__ res,
    float* __restrict__ out, int M, int Kin, int Kout)
{
    __shared__ __align__(16) float As[32][68];
    __shared__ __align__(16) float Bs[32][68];
    const int m0 = blockIdx.x * 64;
    const int c0 = blockIdx.y * 64;
    const int tid = threadIdx.x;
    const int tr = tid >> 4;   // 0..15
    const int tc = tid & 15;   // 0..15

    float acc[4][4];
#pragma unroll
    for (int r = 0; r < 4; r++)
#pragma unroll
        for (int c = 0; c < 4; c++) acc[r][c] = 0.f;

    for (int k0 = 0; k0 < Kin; k0 += 32) {
#pragma unroll
        for (int p = 0; p < 8; p++) {
            int idx = tid + p * 256;             // 0..2047
            if (TRANS_A) {
                int kk = idx >> 6, mm = idx & 63;
                As[kk][mm] = A[(size_t)(k0 + kk) * M + m0 + mm];
            } else {
                int row = idx >> 5, kk = idx & 31;
                As[kk][row] = A[(size_t)(m0 + row) * Kin + k0 + kk];
            }
            int kk2 = idx >> 6, cc = idx & 63;
            Bs[kk2][cc] = W[(size_t)(k0 + kk2) * Kout + c0 + cc];
        }
        __syncthreads();
#pragma unroll
        for (int kk = 0; kk < 32; kk++) {
            float4 a4 = *(const float4*)&As[kk][tr * 4];
            float4 b4 = *(const float4*)&Bs[kk][tc * 4];
            float av[4] = {a4.x, a4.y, a4.z, a4.w};
            float bv[4] = {b4.x, b4.y, b4.z, b4.w};
#pragma unroll
            for (int r = 0; r < 4; r++)
#pragma unroll
                for (int c = 0; c < 4; c++) acc[r][c] += av[r] * bv[c];
        }
        __syncthreads();
    }
#pragma unroll
    for (int r = 0; r < 4; r++) {
#pragma unroll
        for (int c = 0; c < 4; c++) {
            int m = m0 + tr * 4 + r;
            int cc = c0 + tc * 4 + c;
            float v = acc[r][c] + bias[cc];
            if (LEAKY) v = v > 0.f ? v : 0.01f * v;
            if (RES) v += res[(size_t)m * C_DIM + cc];
            if (TRANS_OUT) out[(size_t)cc * M + m] = v;
            else out[(size_t)m * Kout + cc] = v;
        }
    }
}

// ---------------- kernels ----------------

// 3 projections batched over blockIdx.z. grid (36, 2, 3)
__global__ void __launch_bounds__(256) k_proj(
    const float* x0, const float* x1, const float* x2,
    const float* w0, const float* w1, const float* w2,
    const float* b0, const float* b1, const float* b2)
{
    const float* A; const float* W; const float* B; float* O;
    if (blockIdx.z == 0)      { A = x0; W = w0; B = b0; O = g_q; }
    else if (blockIdx.z == 1) { A = x1; W = w1; B = b1; O = g_k; }
    else                      { A = x2; W = w2; B = b2; O = g_v; }
    gemm_body<true, false, false, false>(A, W, B, nullptr, O, N_PIX, C_DIM, C_DIM);
}

// cluster centers from projected k. grid (16), 512 threads
__global__ void __launch_bounds__(512) k_centers(const int* __restrict__ labels)
{
    __shared__ float ssum[4][C_DIM];
    __shared__ int scnt[4];
    const int cl = blockIdx.x;
    const int s = threadIdx.x >> 7;     // 0..3
    const int c = threadIdx.x & 127;
    float sum = 0.f; int cnt = 0;
    const int n0 = s * (N_PIX / 4), n1 = n0 + (N_PIX / 4);
    for (int n = n0; n < n1; n++) {
        if (labels[n] == cl) { sum += g_k[(size_t)n * C_DIM + c]; cnt++; }
    }
    ssum[s][c] = sum;
    if (c == 0) scnt[s] = cnt;
    __syncthreads();
    if (s == 0) {
        float t = ssum[0][c] + ssum[1][c] + ssum[2][c] + ssum[3][c];
        int ct = scnt[0] + scnt[1] + scnt[2] + scnt[3];
        g_centers[cl * C_DIM + c] = t / ((float)ct + 1e-6f);
    }
}

// STABLE counting sort of pixels by label. single block, 256 threads, no atomics.
__global__ void __launch_bounds__(256) k_sort(const int* __restrict__ labels)
{
    __shared__ int cnt[K_CL][257];
    __shared__ int gsum[K_CL][17];
    __shared__ int base[K_CL];
    const int tid = threadIdx.x;
    const int per = N_PIX / 256;   // 9
#pragma unroll
    for (int l = 0; l < K_CL; l++) cnt[l][tid] = 0;
    __syncthreads();
    int myl[9];
#pragma unroll
    for (int u = 0; u < per; u++) {
        int l = labels[tid * per + u];
        myl[u] = l;
        cnt[l][tid]++;
    }
    __syncthreads();
    {
        int l = tid >> 4, g = tid & 15;
        int s = 0;
#pragma unroll
        for (int k2 = 0; k2 < 16; k2++) s += cnt[l][g * 16 + k2];
        gsum[l][g] = s;
    }
    __syncthreads();
    if (tid < K_CL) {
        int run = 0;
        for (int g = 0; g < 16; g++) { int t = gsum[tid][g]; gsum[tid][g] = run; run += t; }
        gsum[tid][16] = run;
    }
    __syncthreads();
    if (tid == 0) {
        int run = 0;
        for (int l = 0; l < K_CL; l++) { base[l] = run; run += gsum[l][16]; }
    }
    __syncthreads();
    {
        int l = tid >> 4, g = tid & 15;
        int run = gsum[l][g];
#pragma unroll
        for (int k2 = 0; k2 < 16; k2++) { int t = cnt[l][g * 16 + k2]; cnt[l][g * 16 + k2] = run; run += t; }
    }
    __syncthreads();
#pragma unroll
    for (int u = 0; u < per; u++) {
        int l = myl[u];
        int p = base[l] + cnt[l][tid]++;
        g_order[p] = tid * per + u;
        g_labs[p] = l;
    }
}

// permute k, v, and pc (both dims) into sorted order. grid (N_PIX), 256 threads
__global__ void __launch_bounds__(256) k_permute(const float* __restrict__ pc)
{
    __shared__ int sord[N_PIX];
    const int tid = threadIdx.x;
    const int ii = blockIdx.x;
    for (int t = tid; t < N_PIX; t += 256) sord[t] = g_order[t];
    __syncthreads();
    const int src = sord[ii];
    if (tid < 128) {
        g_kp[(size_t)ii * C_DIM + tid] = g_k[(size_t)src * C_DIM + tid];
        g_vp[(size_t)ii * C_DIM + tid] = g_v[(size_t)src * C_DIM + tid];
    }
    const float* prow = pc + (size_t)src * N_PIX;
    float* orow = g_pcp + (size_t)ii * N_PIX;
    for (int jj = tid; jj < N_PIX; jj += 256) orow[jj] = prow[sord[jj]];
}

// attention: grid (72, NHEAD), 256 threads = 8 warps, 4 queries per warp.
// Smem tiles amortized 4x per warp; block-precomputed center scores.
__global__ void __launch_bounds__(256, 4) k_attn()
{
    const int h = blockIdx.y, hd = h * HC;
    const int tid = threadIdx.x;
    const int warp = tid >> 5, lane = tid & 31;
    const int ii0 = blockIdx.x * QB;

    __shared__ float vs[2][32][36];
    __shared__ float ks[2][32][36];
    __shared__ __align__(16) float qsm[QB][36];
    __shared__ float cs[QB][K_CL];
    __shared__ __align__(16) float ps[8][QW][36];
    __shared__ int labsm[2][32];
    __shared__ int ordq[QB];
    __shared__ int labq[QB];

    if (tid < QB) {
        ordq[tid] = g_order[ii0 + tid];
        labq[tid] = g_labs[ii0 + tid];
    }
    __syncthreads();
    const int minLab = labq[0];
    const int maxLab = labq[QB - 1];

    // stage scaled q (32 queries x 32 dims)
    for (int idx = tid; idx < QB * 32; idx += 256) {
        int q = idx >> 5, d = idx & 31;
        qsm[q][d] = g_q[(size_t)ordq[q] * C_DIM + hd + d] * INV_SCALE;
    }
    __syncthreads();

    // block-wide center scores cs[q][cl] = q_q . center_cl
    for (int pidx = tid; pidx < QB * K_CL; pidx += 256) {
        int q = pidx >> 4, cl = pidx & 15;
        const float4* cp = (const float4*)(g_centers + cl * C_DIM + hd);
        float s = 0.f;
#pragma unroll
        for (int t = 0; t < 8; t++) {
            float4 f = __ldg(cp + t);
            float4 q4 = *(const float4*)&qsm[q][4 * t];
            s += q4.x * f.x + q4.y * f.y + q4.z * f.z + q4.w * f.w;
        }
        cs[q][cl] = s;
    }

    // per-warp query registers
    int mylab[QW];
    const float* pcrow[QW];
#pragma unroll
    for (int q = 0; q < QW; q++) {
        mylab[q] = labq[warp * QW + q];
        pcrow[q] = g_pcp + (size_t)(ii0 + warp * QW + q) * N_PIX;
    }

    // staging map: thread owns float4 at (row, col4) of the 32x32 tile
    const int row = tid >> 3;
    const int col4 = (tid & 7) * 4;

    // stage chunk 0
    {
        float4 v4 = *(const float4*)&g_vp[(size_t)row * C_DIM + hd + col4];
        *(float4*)&vs[0][row][col4] = v4;
        int l0 = __ldg(&g_labs[0]), l1 = __ldg(&g_labs[31]);
        if (l1 >= minLab && l0 <= maxLab) {
            float4 k4 = *(const float4*)&g_kp[(size_t)row * C_DIM + hd + col4];
            *(float4*)&ks[0][row][col4] = k4;
        }
        if (tid < 32) labsm[0][tid] = g_labs[tid];
    }
    float pccur[QW];
#pragma unroll
    for (int q = 0; q < QW; q++) pccur[q] = __ldg(&pcrow[q][lane]);
    __syncthreads();

    float acc[QW] = {0.f, 0.f, 0.f, 0.f};
    float S[QW] = {0.f, 0.f, 0.f, 0.f};
    int buf = 0;

    for (int ch = 0; ch < NCH; ch++) {
        // prefetch next chunk into registers
        float4 vpre = make_float4(0.f, 0.f, 0.f, 0.f);
        float4 kpre = make_float4(0.f, 0.f, 0.f, 0.f);
        int lpre = 0; bool kneed = false;
        float pcpre[QW] = {0.f, 0.f, 0.f, 0.f};
        if (ch + 1 < NCH) {
            const int j0n = (ch + 1) * 32;
            vpre = *(const float4*)&g_vp[(size_t)(j0n + row) * C_DIM + hd + col4];
            int l0 = __ldg(&g_labs[j0n]), l1 = __ldg(&g_labs[j0n + 31]);
            kneed = (l1 >= minLab && l0 <= maxLab);
            if (kneed)
                kpre = *(const float4*)&g_kp[(size_t)(j0n + row) * C_DIM + hd + col4];
            if (tid < 32) lpre = __ldg(&g_labs[j0n + tid]);
#pragma unroll
            for (int q = 0; q < QW; q++) pcpre[q] = __ldg(&pcrow[q][j0n + lane]);
        }

        // phase 1: lane = key, compute p for all 4 queries
        const int lj = labsm[buf][lane];
        bool sameany = (lj == mylab[0]) | (lj == mylab[1]) |
                       (lj == mylab[2]) | (lj == mylab[3]);
        float d[QW] = {0.f, 0.f, 0.f, 0.f};
        if (__ballot_sync(0xffffffffu, sameany)) {
            // load lane's k-row once, reuse across 4 query dots
#pragma unroll
            for (int t = 0; t < 32; t += 4) {
                float k0 = ks[buf][lane][t + 0];
                float k1 = ks[buf][lane][t + 1];
                float k2 = ks[buf][lane][t + 2];
                float k3 = ks[buf][lane][t + 3];
#pragma unroll
                for (int q = 0; q < QW; q++) {
                    float4 q4 = *(const float4*)&qsm[warp * QW + q][t];
                    d[q] += q4.x * k0 + q4.y * k1 + q4.z * k2 + q4.w * k3;
                }
            }
        }
#pragma unroll
        for (int q = 0; q < QW; q++) {
            float s = (lj == mylab[q]) ? d[q] : cs[warp * QW + q][lj] * pccur[q];
            float p = __expf(s);    // max-free: |s| is O(1) for this workload
            S[q] += p;
            ps[warp][q][lane] = p;
        }
        __syncwarp();

        // phase 2: lane = dim; each vs read feeds 4 FFMAs
#pragma unroll
        for (int jq = 0; jq < 32; jq += 4) {
            float v0 = vs[buf][jq + 0][lane];
            float v1 = vs[buf][jq + 1][lane];
            float v2 = vs[buf][jq + 2][lane];
            float v3 = vs[buf][jq + 3][lane];
#pragma unroll
            for (int q = 0; q < QW; q++) {
                float4 p4 = *(const float4*)&ps[warp][q][jq];
                acc[q] += p4.x * v0 + p4.y * v1 + p4.z * v2 + p4.w * v3;
            }
        }

        // commit prefetched chunk into the other buffer
        if (ch + 1 < NCH) {
            const int nb = buf ^ 1;
            *(float4*)&vs[nb][row][col4] = vpre;
            if (kneed) *(float4*)&ks[nb][row][col4] = kpre;
            if (tid < 32) labsm[nb][tid] = lpre;
#pragma unroll
            for (int q = 0; q < QW; q++) pccur[q] = pcpre[q];
        }
        buf ^= 1;
        __syncthreads();
    }

#pragma unroll
    for (int q = 0; q < QW; q++) {
        float s = S[q];
#pragma unroll
        for (int off = 16; off; off >>= 1) s += __shfl_xor_sync(0xffffffffu, s, off);
        g_attn[(size_t)ordq[warp * QW + q] * C_DIM + hd + lane] = acc[q] / s;
    }
}

// MLP stages
__global__ void __launch_bounds__(256) k_mlp1a(const float* W, const float* b) {
    gemm_body<false, true, false, false>(g_attn, W, b, nullptr, g_h1, N_PIX, 128, 256);
}
__global__ void __launch_bounds__(256) k_mlp1b(const float* W, const float* b) {
    gemm_body<false, false, true, false>(g_h1, W, b, g_v, g_rs1, N_PIX, 256, 128);
}
__global__ void __launch_bounds__(256) k_mlp2a(const float* W, const float* b) {
    gemm_body<false, true, false, false>(g_rs1, W, b, nullptr, g_h2, N_PIX, 128, 256);
}
__global__ void __launch_bounds__(256) k_mlp2b(const float* W, const float* b, float* o) {
    gemm_body<false, false, true, true>(g_h2, W, b, g_rs1, o, N_PIX, 256, 128);
}

// ---------------- launch ----------------
extern "C" void kernel_launch(void* const* d_in, const int* in_sizes, int n_in,
                              void* d_out, int out_size)
{
    const float* q_img  = (const float*)d_in[0];
    const float* k_img  = (const float*)d_in[1];
    const float* v_img  = (const float*)d_in[2];
    const float* pc     = (const float*)d_in[3];
    const int*   labels = (const int*)  d_in[4];
    const float* wq  = (const float*)d_in[5];
    const float* bq  = (const float*)d_in[6];
    const float* wk  = (const float*)d_in[7];
    const float* bk  = (const float*)d_in[8];
    const float* wv  = (const float*)d_in[9];
    const float* bv  = (const float*)d_in[10];
    const float* w1a = (const float*)d_in[11];
    const float* b1a = (const float*)d_in[12];
    const float* w1b = (const float*)d_in[13];
    const float* b1b = (const float*)d_in[14];
    const float* w2a = (const float*)d_in[15];
    const float* b2a = (const float*)d_in[16];
    const float* w2b = (const float*)d_in[17];
    const float* b2b = (const float*)d_in[18];
    float* out = (float*)d_out;

    dim3 gproj(N_PIX / 64, 2, 3);
    k_proj<<<gproj, 256>>>(q_img, k_img, v_img, wq, wk, wv, bq, bk, bv);
    k_centers<<<K_CL, 512>>>(labels);
    k_sort<<<1, 256>>>(labels);
    k_permute<<<N_PIX, 256>>>(pc);
    dim3 gattn(N_PIX / QB, NHEAD);
    k_attn<<<gattn, 256>>>();
    k_mlp1a<<<dim3(N_PIX / 64, 4), 256>>>(w1a, b1a);
    k_mlp1b<<<dim3(N_PIX / 64, 2), 256>>>(w1b, b1b);
    k_mlp2a<<<dim3(N_PIX / 64, 4), 256>>>(w2a, b2a);
    k_mlp2b<<<dim3(N_PIX / 64, 2), 256>>>(w2b, b2b, out);
}